// round 1
// baseline (speedup 1.0000x reference)
#include <cuda_runtime.h>
#include <cuda_bf16.h>
#include <cstdint>

// Problem constants (fixed by the reference generator)
#define F_DIM 16
#define B_GRAPHS 8
#define NVALS 9               // base + 8 segment dots
#define ACC_BLOCKS 2048
#define ACC_THREADS 256

// Scratch for per-block partials. Written fully on every replay -> no zeroing needed.
__device__ float g_partials[ACC_BLOCKS * NVALS];

__global__ __launch_bounds__(ACC_THREADS) void accum_kernel(
    const float* __restrict__ inp,
    const float* __restrict__ tgt,
    const int* __restrict__ batch,
    int n)
{
    float base = 0.0f;
    float dots[B_GRAPHS];
#pragma unroll
    for (int b = 0; b < B_GRAPHS; b++) dots[b] = 0.0f;

    const int stride = gridDim.x * blockDim.x;
    for (int i = blockIdx.x * blockDim.x + threadIdx.x; i < n; i += stride) {
        const float4* a = reinterpret_cast<const float4*>(inp + (size_t)i * F_DIM);
        const float4* t = reinterpret_cast<const float4*>(tgt + (size_t)i * F_DIM);
        float dot = 0.0f, sq = 0.0f;
#pragma unroll
        for (int j = 0; j < 4; j++) {
            float4 x = a[j];
            float4 y = t[j];
            sq  = fmaf(x.x, x.x, sq);  sq = fmaf(x.y, x.y, sq);
            sq  = fmaf(x.z, x.z, sq);  sq = fmaf(x.w, x.w, sq);
            sq  = fmaf(y.x, y.x, sq);  sq = fmaf(y.y, y.y, sq);
            sq  = fmaf(y.z, y.z, sq);  sq = fmaf(y.w, y.w, sq);
            dot = fmaf(x.x, y.x, dot); dot = fmaf(x.y, y.y, dot);
            dot = fmaf(x.z, y.z, dot); dot = fmaf(x.w, y.w, dot);
        }
        base += sq;
        int bid = batch[i] & (B_GRAPHS - 1);
        // predicated adds (unrolled) — avoids local-memory spill from dynamic indexing
#pragma unroll
        for (int b = 0; b < B_GRAPHS; b++) {
            if (bid == b) dots[b] += dot;
        }
    }

    // pack the 9 values and reduce
    float vals[NVALS];
    vals[0] = base;
#pragma unroll
    for (int b = 0; b < B_GRAPHS; b++) vals[b + 1] = dots[b];

    // warp reduce
#pragma unroll
    for (int k = 0; k < NVALS; k++) {
#pragma unroll
        for (int off = 16; off > 0; off >>= 1)
            vals[k] += __shfl_down_sync(0xFFFFFFFFu, vals[k], off);
    }

    __shared__ float smem[ACC_THREADS / 32][NVALS];
    int warp = threadIdx.x >> 5;
    int lane = threadIdx.x & 31;
    if (lane == 0) {
#pragma unroll
        for (int k = 0; k < NVALS; k++) smem[warp][k] = vals[k];
    }
    __syncthreads();

    if (threadIdx.x == 0) {
        float out[NVALS];
#pragma unroll
        for (int k = 0; k < NVALS; k++) out[k] = smem[0][k];
#pragma unroll
        for (int w = 1; w < ACC_THREADS / 32; w++) {
#pragma unroll
            for (int k = 0; k < NVALS; k++) out[k] += smem[w][k];
        }
#pragma unroll
        for (int k = 0; k < NVALS; k++)
            g_partials[blockIdx.x * NVALS + k] = out[k];
    }
}

__global__ __launch_bounds__(256) void finalize_kernel(float* __restrict__ out)
{
    float vals[NVALS];
#pragma unroll
    for (int k = 0; k < NVALS; k++) vals[k] = 0.0f;

    for (int r = threadIdx.x; r < ACC_BLOCKS; r += 256) {
#pragma unroll
        for (int k = 0; k < NVALS; k++)
            vals[k] += g_partials[r * NVALS + k];
    }

#pragma unroll
    for (int k = 0; k < NVALS; k++) {
#pragma unroll
        for (int off = 16; off > 0; off >>= 1)
            vals[k] += __shfl_down_sync(0xFFFFFFFFu, vals[k], off);
    }

    __shared__ float smem[8][NVALS];
    int warp = threadIdx.x >> 5;
    int lane = threadIdx.x & 31;
    if (lane == 0) {
#pragma unroll
        for (int k = 0; k < NVALS; k++) smem[warp][k] = vals[k];
    }
    __syncthreads();

    if (threadIdx.x == 0) {
        float acc[NVALS];
#pragma unroll
        for (int k = 0; k < NVALS; k++) acc[k] = smem[0][k];
#pragma unroll
        for (int w = 1; w < 8; w++) {
#pragma unroll
            for (int k = 0; k < NVALS; k++) acc[k] += smem[w][k];
        }
        // min over all 2^B sign combos == base - 2 * sum_b |dot_b|
        float base = acc[0];
        float s = 0.0f;
#pragma unroll
        for (int b = 0; b < B_GRAPHS; b++) s += fabsf(acc[b + 1]);
        out[0] = base - 2.0f * s;
    }
}

extern "C" void kernel_launch(void* const* d_in, const int* in_sizes, int n_in,
                              void* d_out, int out_size)
{
    const float* inp   = (const float*)d_in[0];
    const float* tgt   = (const float*)d_in[1];
    const int*   batch = (const int*)d_in[2];
    float* out = (float*)d_out;

    int n = in_sizes[2];  // number of nodes (batch vector length)

    accum_kernel<<<ACC_BLOCKS, ACC_THREADS>>>(inp, tgt, batch, n);
    finalize_kernel<<<1, 256>>>(out);
}